// round 4
// baseline (speedup 1.0000x reference)
#include <cuda_runtime.h>
#include <cstdint>
#include <cstddef>

#define BB 8
#define LL 2048
#define HH 256
#define ROWS 64
#define JT 32
#define NT (LL / JT)
#define PDST 34           // Psd row stride in ull (=17 ulonglong2, 16B aligned rows)
#define WST 258

typedef unsigned long long ull;

// -------- scratch (no allocations allowed: __device__ globals) --------
__device__ float g_base[LL];
__device__ float g_st[BB * LL];
__device__ float g_so[BB * LL];
__device__ float g_mult[BB * LL];

// ---------------------------------------------------------------------
// f32x2 helpers (Blackwell packed fp32 pipe)
// ---------------------------------------------------------------------
__device__ __forceinline__ ull pack_dup(float p) {
    ull r;
    asm("mov.b64 %0, {%1, %1};" : "=l"(r) : "f"(p));
    return r;
}
__device__ __forceinline__ void fma2(ull& d, ull a, ull b) {
    asm("fma.rn.f32x2 %0, %1, %2, %0;" : "+l"(d) : "l"(a), "l"(b));
}
__device__ __forceinline__ void mul2(ull& d, ull a) {
    asm("mul.rn.f32x2 %0, %0, %1;" : "+l"(d) : "l"(a));
}
__device__ __forceinline__ void unpack2(ull v, float& lo, float& hi) {
    asm("mov.b64 {%0, %1}, %2;" : "=f"(lo), "=f"(hi) : "l"(v));
}

// ---------------------------------------------------------------------
// Kernel 0: base table + per-token column multiplier
// ---------------------------------------------------------------------
__global__ void k_base_mult(const int* __restrict__ pos) {
    int i = blockIdx.x * blockDim.x + threadIdx.x;
    if (i < LL) {
        g_base[i] = (i == 0) ? 0.5f : (1.0f / log2f(2.0f + (float)i));
    }
    if (i < BB * LL) {
        const unsigned long long mask =
            (1ULL << 19) | (1ULL << 20) | (1ULL << 21) |
            (1ULL << 33) | (1ULL << 34) | (1ULL << 35) |
            (1ULL << 41) | (1ULL << 42) | (1ULL << 43) |
            (1ULL << 44) | (1ULL << 45) | (1ULL << 46);
        int p = pos[i];
        bool op = (p >= 0) && (p < 64) && (((mask >> p) & 1ULL) != 0ULL);
        g_mult[i] = op ? 8.0f : 1.0f;
    }
}

// ---------------------------------------------------------------------
// Kernel 1: fused per-token transforms (y=0 -> st, y=1 -> so)
// 32 tokens x 256 h per CTA, 256 threads.
// ---------------------------------------------------------------------
__global__ __launch_bounds__(256)
void k_transform2(const float* __restrict__ text, const float* __restrict__ opinion,
                  const float* __restrict__ Wt, const float* __restrict__ bt,
                  const float* __restrict__ Wo, const float* __restrict__ wa,
                  const float* __restrict__ ba) {
    __shared__ float Ws[32 * WST];
    __shared__ float Xs[32 * 36];
    __shared__ float bias_s[256];
    __shared__ float wa_s[256];

    int which = blockIdx.y;
    const float* X = which ? opinion : text;
    const float* W = which ? Wo : Wt;
    const float* wav = which ? (wa + HH) : wa;

    int tid = threadIdx.x;
    int tx = tid & 31, ty = tid >> 5;
    int tok0 = blockIdx.x * 32;

    bias_s[tid] = which ? 0.0f : bt[tid];
    wa_s[tid] = wav[tid];

    ull acc2[4][4];
#pragma unroll
    for (int q = 0; q < 4; ++q)
#pragma unroll
        for (int m = 0; m < 4; ++m) acc2[q][m] = 0ULL;

    int kkl = tid & 31;
    int hb = tid >> 5;

    for (int k0 = 0; k0 < 256; k0 += 32) {
        __syncthreads();
#pragma unroll
        for (int r = 0; r < 32; ++r) {
            int h = hb + r * 8;
            Ws[kkl * WST + h] = W[h * 256 + k0 + kkl];
        }
#pragma unroll
        for (int r = 0; r < 4; ++r) {
            int idx = r * 256 + tid;
            int tok = idx >> 5, kk = idx & 31;
            Xs[tok * 36 + kk] = X[(size_t)(tok0 + tok) * 256 + k0 + kk];
        }
        __syncthreads();
#pragma unroll 8
        for (int kk = 0; kk < 32; ++kk) {
            ull wv[4];
#pragma unroll
            for (int m = 0; m < 4; ++m)
                wv[m] = *(const ull*)(Ws + kk * WST + tx * 2 + 64 * m);
            ull xd[4];
#pragma unroll
            for (int q = 0; q < 4; ++q)
                xd[q] = pack_dup(Xs[(ty * 4 + q) * 36 + kk]);
#pragma unroll
            for (int q = 0; q < 4; ++q)
#pragma unroll
                for (int m = 0; m < 4; ++m)
                    fma2(acc2[q][m], xd[q], wv[m]);
        }
    }

    float e = which ? ba[0] : 0.0f;
    float part[4];
#pragma unroll
    for (int q = 0; q < 4; ++q) {
        float s = 0.0f;
#pragma unroll
        for (int m = 0; m < 4; ++m) {
            int h = tx * 2 + 64 * m;
            float a0, a1;
            unpack2(acc2[q][m], a0, a1);
            s += tanhf(a0 + bias_s[h]) * wa_s[h];
            s += tanhf(a1 + bias_s[h + 1]) * wa_s[h + 1];
        }
        part[q] = s;
    }
#pragma unroll
    for (int off = 16; off; off >>= 1) {
#pragma unroll
        for (int q = 0; q < 4; ++q)
            part[q] += __shfl_xor_sync(0xffffffffu, part[q], off);
    }
    if (tx == 0) {
        float* outp = which ? g_so : g_st;
#pragma unroll
        for (int q = 0; q < 4; ++q)
            outp[tok0 + ty * 4 + q] = part[q] + e;
    }
}

// ---------------------------------------------------------------------
// Kernel 2: flash attention. 64 rows/CTA, JT=32 (2 CTAs/SM), 8x8 tile,
// P stored pre-duplicated ({p,p} ull) so PV loop is pure fma2 + LDS.
// ---------------------------------------------------------------------
__device__ __forceinline__ void cp16(float* s, const float* g) {
    unsigned sa = (unsigned)__cvta_generic_to_shared(s);
    asm volatile("cp.async.cg.shared.global [%0], [%1], 16;\n" ::"r"(sa), "l"(g));
}

__global__ __launch_bounds__(256, 2)
void k_attn(const float* __restrict__ V, float* __restrict__ out) {
    extern __shared__ float sm[];
    float* Vs = sm;                          // 2 * 32 * 256 = 16384 floats
    ull* Psd = (ull*)(Vs + 2 * JT * HH);     // 64 * 34 ull = 4352 floats
    float* base_s = (float*)(Psd + ROWS * PDST);  // 2048
    float* M_s = base_s + LL;                // 64
    float* S_s = M_s + ROWS;                 // 64
    float* F_s = S_s + ROWS;                 // 64

    int tid = threadIdx.x;
    int tx = tid & 31, ty = tid >> 5;
    int b = blockIdx.x >> 5;
    int row0 = (blockIdx.x & 31) * ROWS;

    const float* Vg = V + (size_t)b * LL * HH;
    const float* sog = g_so + b * LL;
    const float* mug = g_mult + b * LL;

    for (int i = tid; i < LL; i += 256) base_s[i] = g_base[i];
    if (tid < ROWS) { M_s[tid] = -1e30f; S_s[tid] = 0.0f; }

    // prefetch tile 0 into buffer 0  (tile = 32 j x 256 feat = 32KB)
#pragma unroll
    for (int r = 0; r < 8; ++r) {
        int c = r * 256 + tid;
        cp16(Vs + c * 4, Vg + c * 4);
    }
    asm volatile("cp.async.commit_group;\n");

    // score mapping: 4 threads per row, 8 consecutive j each
    int sr = tid >> 2;              // 0..63
    int sjo = (tid & 3) * 8;
    float sti = g_st[b * LL + row0 + sr];
    int gi = row0 + sr;

    ull acc[8][4];
#pragma unroll
    for (int r = 0; r < 8; ++r)
#pragma unroll
        for (int m = 0; m < 4; ++m) acc[r][m] = 0ULL;

    __syncthreads();

    for (int t = 0; t < NT; ++t) {
        if (t) __syncthreads();
        int j0 = t * JT;

        // ---- score phase: 8 scores per thread ----
        float4 s4a = *(const float4*)(sog + j0 + sjo);
        float4 s4b = *(const float4*)(sog + j0 + sjo + 4);
        float4 m4a = *(const float4*)(mug + j0 + sjo);
        float4 m4b = *(const float4*)(mug + j0 + sjo + 4);
        float sov[8] = {s4a.x, s4a.y, s4a.z, s4a.w, s4b.x, s4b.y, s4b.z, s4b.w};
        float muv[8] = {m4a.x, m4a.y, m4a.z, m4a.w, m4b.x, m4b.y, m4b.z, m4b.w};

        float s[8];
        float lm = -1e30f;
#pragma unroll
        for (int u = 0; u < 8; ++u) {
            int j = j0 + sjo + u;
            int d = gi - j; d = (d < 0) ? -d : d;
            float sc = (sti + sov[u]) * base_s[d] * muv[u];
            s[u] = sc;
            lm = fmaxf(lm, sc);
        }
        lm = fmaxf(lm, __shfl_xor_sync(0xffffffffu, lm, 1));
        lm = fmaxf(lm, __shfl_xor_sync(0xffffffffu, lm, 2));
        float Mold = M_s[sr];
        float Mn = fmaxf(Mold, lm);
        float ls = 0.0f;
#pragma unroll
        for (int u = 0; u < 8; ++u) {
            float p = __expf(s[u] - Mn);
            Psd[sr * PDST + sjo + u] = pack_dup(p);   // duplicated pair store
            ls += p;
        }
        ls += __shfl_xor_sync(0xffffffffu, ls, 1);
        ls += __shfl_xor_sync(0xffffffffu, ls, 2);
        if ((tid & 3) == 0) {
            float f = __expf(Mold - Mn);
            F_s[sr] = f;
            M_s[sr] = Mn;
            S_s[sr] = S_s[sr] * f + ls;
        }

        // ---- prefetch next V tile ----
        if (t + 1 < NT) {
            float* Vn = Vs + ((t + 1) & 1) * JT * HH;
            const float* gs = Vg + (size_t)(j0 + JT) * HH;
#pragma unroll
            for (int r = 0; r < 8; ++r) {
                int c = r * 256 + tid;
                cp16(Vn + c * 4, gs + c * 4);
            }
            asm volatile("cp.async.commit_group;\n");
            asm volatile("cp.async.wait_group 1;\n");
        } else {
            asm volatile("cp.async.wait_group 0;\n");
        }
        __syncthreads();  // V tile + Psd + F_s visible

        // ---- PV phase: 8 rows x 8 feats per thread, j in pairs ----
        const ulonglong2* V2 = (const ulonglong2*)(Vs + (t & 1) * JT * HH);
        const ulonglong2* Pdd = (const ulonglong2*)Psd;
#pragma unroll
        for (int r = 0; r < 8; ++r) {
            ull fd = pack_dup(F_s[ty * 8 + r]);
#pragma unroll
            for (int m = 0; m < 4; ++m) mul2(acc[r][m], fd);
        }
        int prow = ty * 8 * (PDST / 2);   // row stride in ulonglong2 = 17
#pragma unroll 4
        for (int j2 = 0; j2 < JT / 2; ++j2) {
            // V for the two j's of this pair
            ulonglong2 va0 = V2[(size_t)(2 * j2) * 64 + tx * 2];
            ulonglong2 va1 = V2[(size_t)(2 * j2) * 64 + tx * 2 + 1];
            ulonglong2 vb0 = V2[(size_t)(2 * j2 + 1) * 64 + tx * 2];
            ulonglong2 vb1 = V2[(size_t)(2 * j2 + 1) * 64 + tx * 2 + 1];
#pragma unroll
            for (int r = 0; r < 8; ++r) {
                ulonglong2 pp = Pdd[prow + r * (PDST / 2) + j2];  // {pj,pj},{pj+1,pj+1}
                fma2(acc[r][0], pp.x, va0.x);
                fma2(acc[r][1], pp.x, va0.y);
                fma2(acc[r][2], pp.x, va1.x);
                fma2(acc[r][3], pp.x, va1.y);
                fma2(acc[r][0], pp.y, vb0.x);
                fma2(acc[r][1], pp.y, vb0.y);
                fma2(acc[r][2], pp.y, vb1.x);
                fma2(acc[r][3], pp.y, vb1.y);
            }
        }
    }

    // ---- epilogue: normalize and store ----
    float* Ob = out + ((size_t)b * LL + row0) * HH;
#pragma unroll
    for (int r = 0; r < 8; ++r) {
        int row = ty * 8 + r;
        float inv = 1.0f / S_s[row];
        float4 o0, o1;
        unpack2(acc[r][0], o0.x, o0.y);
        unpack2(acc[r][1], o0.z, o0.w);
        unpack2(acc[r][2], o1.x, o1.y);
        unpack2(acc[r][3], o1.z, o1.w);
        o0.x *= inv; o0.y *= inv; o0.z *= inv; o0.w *= inv;
        o1.x *= inv; o1.y *= inv; o1.z *= inv; o1.w *= inv;
        float4* O4 = (float4*)(Ob + (size_t)row * HH + tx * 8);
        O4[0] = o0;
        O4[1] = o1;
    }
}

// ---------------------------------------------------------------------
extern "C" void kernel_launch(void* const* d_in, const int* in_sizes, int n_in,
                              void* d_out, int out_size) {
    const float* opinion = (const float*)d_in[0];
    const float* text    = (const float*)d_in[1];
    const int*   pos     = (const int*)d_in[2];
    const float* Wt      = (const float*)d_in[3];
    const float* bt      = (const float*)d_in[4];
    const float* Wo      = (const float*)d_in[5];
    const float* wa      = (const float*)d_in[6];
    const float* ba      = (const float*)d_in[7];
    float* out = (float*)d_out;

    const int attn_smem =
        (2 * JT * HH) * 4 + (ROWS * PDST) * 8 + (LL + 3 * ROWS) * 4;
    cudaFuncSetAttribute(k_attn, cudaFuncAttributeMaxDynamicSharedMemorySize,
                         attn_smem);

    k_base_mult<<<(BB * LL + 255) / 256, 256>>>(pos);
    k_transform2<<<dim3(BB * LL / 32, 2), 256>>>(text, opinion, Wt, bt, Wo, wa, ba);
    k_attn<<<BB * (LL / ROWS), 256, attn_smem>>>(opinion, out);
}